// round 1
// baseline (speedup 1.0000x reference)
#include <cuda_runtime.h>
#include <cstdint>

// Problem constants (GCNEncoder: N=100000, E=3200000, 128 -> 16 -> 64)
#define NMAX   100000
#define IN_C   128
#define HID    16
#define OUTC   64

// ---------------- scratch (no allocations allowed -> __device__ globals) ----
__device__ float g_dinv[NMAX];            // deg accumulator, then rsqrt(deg+1)
__device__ float g_h1  [NMAX * HID];      // x @ W1
__device__ float g_a1  [NMAX * HID];      // layer-1 aggregation, then relu output
__device__ float g_h2  [NMAX * OUTC];     // relu(out1) @ W2
__device__ int   g_is32;                  // 1 if edge_index is really int32

// ---------------- helpers ---------------------------------------------------
__device__ __forceinline__ void red_add_f4(float* addr, float x, float y, float z, float w) {
    asm volatile("red.global.add.v4.f32 [%0], {%1,%2,%3,%4};"
                 :: "l"(addr), "f"(x), "f"(y), "f"(z), "f"(w) : "memory");
}

__device__ __forceinline__ void load_edge(const void* ei, long long E, long long e,
                                          int is32, long long& r, long long& c) {
    if (is32) {
        const int* p = (const int*)ei;
        r = p[e]; c = p[E + e];
    } else {
        const long long* p = (const long long*)ei;
        r = p[e]; c = p[E + e];
    }
}

// ---------------- kernels ----------------------------------------------------

// Sniff index dtype: if any of the first 1024 int64-words is >= N, data is int32.
__global__ void detect_kernel(const void* ei, long long words, long long n_nodes) {
    __shared__ int s;
    if (threadIdx.x == 0) s = 0;
    __syncthreads();
    long long cnt = words < 1024 ? words : 1024;
    const long long* p = (const long long*)ei;
    for (long long i = threadIdx.x; i < cnt; i += blockDim.x) {
        if ((unsigned long long)p[i] >= (unsigned long long)n_nodes) s = 1;
    }
    __syncthreads();
    if (threadIdx.x == 0) g_is32 = s;
}

// In-degree count (targets = col). Self loop handled in dinv_kernel (+1).
__global__ void deg_kernel(const void* ei, long long E) {
    long long e = (long long)blockIdx.x * blockDim.x + threadIdx.x;
    if (e >= E) return;
    int is32 = g_is32;
    long long c;
    if (is32) c = ((const int*)ei)[E + e];
    else      c = ((const long long*)ei)[E + e];
    atomicAdd(&g_dinv[c], 1.0f);
}

__global__ void dinv_kernel(long long Nn) {
    long long i = (long long)blockIdx.x * blockDim.x + threadIdx.x;
    if (i >= Nn) return;
    g_dinv[i] = rsqrtf(g_dinv[i] + 1.0f);
}

// h1 = x @ W1   (per-thread row, W1 staged in shared)
__global__ void mm1_kernel(const float* __restrict__ x, const float* __restrict__ W1,
                           long long Nn) {
    __shared__ float Ws[IN_C * HID];
    for (int i = threadIdx.x; i < IN_C * HID; i += blockDim.x) Ws[i] = W1[i];
    __syncthreads();
    long long r = (long long)blockIdx.x * blockDim.x + threadIdx.x;
    if (r >= Nn) return;
    float acc[HID];
#pragma unroll
    for (int j = 0; j < HID; j++) acc[j] = 0.f;
    const float4* xr = (const float4*)(x + r * IN_C);
#pragma unroll 4
    for (int k = 0; k < IN_C / 4; k++) {
        float4 v = xr[k];
        const float* w = &Ws[(k * 4) * HID];
#pragma unroll
        for (int j = 0; j < HID; j++)
            acc[j] += v.x * w[j] + v.y * w[HID + j] + v.z * w[2 * HID + j] + v.w * w[3 * HID + j];
    }
    float4* o = (float4*)&g_h1[r * HID];
#pragma unroll
    for (int q = 0; q < HID / 4; q++)
        o[q] = make_float4(acc[4 * q], acc[4 * q + 1], acc[4 * q + 2], acc[4 * q + 3]);
}

// Layer-1 edge scatter: a1[c] += h1[r] * dinv[r]*dinv[c]   (one thread per edge)
__global__ void agg1_kernel(const void* ei, long long E) {
    long long e = (long long)blockIdx.x * blockDim.x + threadIdx.x;
    if (e >= E) return;
    int is32 = g_is32;
    long long r, c;
    load_edge(ei, E, e, is32, r, c);
    float norm = g_dinv[r] * g_dinv[c];
    const float4* h = (const float4*)&g_h1[r * HID];
    float* dst = &g_a1[c * HID];
#pragma unroll
    for (int q = 0; q < HID / 4; q++) {
        float4 v = h[q];
        red_add_f4(dst + 4 * q, v.x * norm, v.y * norm, v.z * norm, v.w * norm);
    }
}

// out1 = relu(a1 + h1*dinv^2 + b1), written back into g_a1
__global__ void fin1_kernel(const float* __restrict__ b1, long long Nn) {
    long long i = (long long)blockIdx.x * blockDim.x + threadIdx.x;
    if (i >= Nn) return;
    float d = g_dinv[i];
    float s = d * d;
#pragma unroll
    for (int j = 0; j < HID; j++) {
        float v = g_a1[i * HID + j] + g_h1[i * HID + j] * s + b1[j];
        g_a1[i * HID + j] = v > 0.f ? v : 0.f;
    }
}

// h2 = out1 @ W2   (per-thread row)
__global__ void mm2_kernel(const float* __restrict__ W2, long long Nn) {
    __shared__ float Ws[HID * OUTC];
    for (int i = threadIdx.x; i < HID * OUTC; i += blockDim.x) Ws[i] = W2[i];
    __syncthreads();
    long long r = (long long)blockIdx.x * blockDim.x + threadIdx.x;
    if (r >= Nn) return;
    float xin[HID];
    const float4* src = (const float4*)&g_a1[r * HID];
#pragma unroll
    for (int q = 0; q < HID / 4; q++) {
        float4 v = src[q];
        xin[4 * q] = v.x; xin[4 * q + 1] = v.y; xin[4 * q + 2] = v.z; xin[4 * q + 3] = v.w;
    }
    float acc[OUTC];
#pragma unroll
    for (int j = 0; j < OUTC; j++) acc[j] = 0.f;
#pragma unroll
    for (int k = 0; k < HID; k++) {
        float xv = xin[k];
        const float* w = &Ws[k * OUTC];
#pragma unroll
        for (int j = 0; j < OUTC; j++) acc[j] += xv * w[j];
    }
    float4* o = (float4*)&g_h2[r * OUTC];
#pragma unroll
    for (int q = 0; q < OUTC / 4; q++)
        o[q] = make_float4(acc[4 * q], acc[4 * q + 1], acc[4 * q + 2], acc[4 * q + 3]);
}

// Layer-2 edge scatter: out[c] += h2[r] * norm   (4 threads per edge, 64B each)
__global__ void agg2_kernel(const void* ei, float* __restrict__ out, long long E) {
    long long t = (long long)blockIdx.x * blockDim.x + threadIdx.x;
    long long e = t >> 2;
    int q = (int)(t & 3);
    if (e >= E) return;
    int is32 = g_is32;
    long long r, c;
    load_edge(ei, E, e, is32, r, c);
    float norm = g_dinv[r] * g_dinv[c];
    const float4* h = (const float4*)&g_h2[r * OUTC + q * 16];
    float* dst = out + c * OUTC + q * 16;
#pragma unroll
    for (int u = 0; u < 4; u++) {
        float4 v = h[u];
        red_add_f4(dst + 4 * u, v.x * norm, v.y * norm, v.z * norm, v.w * norm);
    }
}

// out += h2*dinv^2 + b2
__global__ void fin2_kernel(const float* __restrict__ b2, float* __restrict__ out,
                            long long Nn) {
    long long i = (long long)blockIdx.x * blockDim.x + threadIdx.x;
    if (i >= Nn) return;
    float d = g_dinv[i];
    float s = d * d;
#pragma unroll
    for (int j = 0; j < OUTC; j++) {
        out[i * OUTC + j] += g_h2[i * OUTC + j] * s + b2[j];
    }
}

// ---------------- launch ----------------------------------------------------
extern "C" void kernel_launch(void* const* d_in, const int* in_sizes, int n_in,
                              void* d_out, int out_size) {
    const float* x  = (const float*)d_in[0];
    const void*  ei = d_in[1];
    const float* W1 = (const float*)d_in[2];
    const float* b1 = (const float*)d_in[3];
    const float* W2 = (const float*)d_in[4];
    const float* b2 = (const float*)d_in[5];
    float* out = (float*)d_out;

    long long Nn = in_sizes[0] / IN_C;
    long long E  = (long long)in_sizes[1] / 2;

    float* p_dinv; cudaGetSymbolAddress((void**)&p_dinv, g_dinv);
    float* p_a1;   cudaGetSymbolAddress((void**)&p_a1,   g_a1);

    cudaMemsetAsync(p_dinv, 0, Nn * sizeof(float));
    cudaMemsetAsync(p_a1,   0, Nn * HID * sizeof(float));
    cudaMemsetAsync(out,    0, Nn * OUTC * sizeof(float));

    detect_kernel<<<1, 256>>>(ei, E, Nn);

    int T = 256;
    deg_kernel <<<(unsigned)((E + T - 1) / T), T>>>(ei, E);
    dinv_kernel<<<(unsigned)((Nn + T - 1) / T), T>>>(Nn);

    mm1_kernel<<<(unsigned)((Nn + 127) / 128), 128>>>(x, W1, Nn);
    agg1_kernel<<<(unsigned)((E + T - 1) / T), T>>>(ei, E);
    fin1_kernel<<<(unsigned)((Nn + T - 1) / T), T>>>(b1, Nn);

    mm2_kernel<<<(unsigned)((Nn + 127) / 128), 128>>>(W2, Nn);
    agg2_kernel<<<(unsigned)((4 * E + T - 1) / T), T>>>(ei, out, E);
    fin2_kernel<<<(unsigned)((Nn + T - 1) / T), T>>>(b2, out, Nn);
}

// round 2
// speedup vs baseline: 2.0868x; 2.0868x over previous
#include <cuda_runtime.h>
#include <cstdint>

// GCNEncoder: N=100000, E=3200000, 128 -> 16 -> 64
#define NMAX   100000
#define IN_C   128
#define HID    16
#define OUTC   64
#define MMTILE 64   // rows per block in the GEMM kernels

// ---------------- scratch (__device__ globals; no allocations allowed) ------
__device__ float g_dinv[NMAX];            // deg accumulator, then rsqrt(deg+1)
__device__ float g_h1s [NMAX * HID];      // (x @ W1) * dinv[row]
__device__ float g_a1  [NMAX * HID];      // layer-1 aggregation
__device__ float g_zs  [NMAX * HID];      // relu(out1) * dinv[row]
__device__ float g_a2  [NMAX * HID];      // layer-2 aggregation (16-dim!)
__device__ int   g_is32;                  // 1 if edge_index is really int32

// ---------------- helpers ---------------------------------------------------
__device__ __forceinline__ void red_add_f4(float* addr, float4 v) {
    asm volatile("red.global.add.v4.f32 [%0], {%1,%2,%3,%4};"
                 :: "l"(addr), "f"(v.x), "f"(v.y), "f"(v.z), "f"(v.w) : "memory");
}

// ---------------- kernels ----------------------------------------------------

// Sniff index dtype: if any of the first 1024 int64-words is >= N, data is int32.
__global__ void detect_kernel(const void* ei, long long words, long long n_nodes) {
    __shared__ int s;
    if (threadIdx.x == 0) s = 0;
    __syncthreads();
    long long cnt = words < 1024 ? words : 1024;
    const long long* p = (const long long*)ei;
    for (long long i = threadIdx.x; i < cnt; i += blockDim.x) {
        if ((unsigned long long)p[i] >= (unsigned long long)n_nodes) s = 1;
    }
    __syncthreads();
    if (threadIdx.x == 0) g_is32 = s;
}

// In-degree count (targets = col). Self loop handled in dinv_kernel (+1).
__global__ void deg_kernel(const void* ei, long long E) {
    long long e = (long long)blockIdx.x * blockDim.x + threadIdx.x;
    if (e >= E) return;
    long long c;
    if (g_is32) c = ((const int*)ei)[E + e];
    else        c = ((const long long*)ei)[E + e];
    atomicAdd(&g_dinv[c], 1.0f);
}

__global__ void dinv_kernel(long long Nn) {
    long long i = (long long)blockIdx.x * blockDim.x + threadIdx.x;
    if (i >= Nn) return;
    g_dinv[i] = rsqrtf(g_dinv[i] + 1.0f);
}

// h1s = (x @ W1) * dinv[row].  Coalesced smem-staged tile, 4 threads/row.
__global__ __launch_bounds__(256) void mm1_kernel(const float* __restrict__ x,
                                                  const float* __restrict__ W1,
                                                  long long Nn) {
    __shared__ float xs[MMTILE][IN_C + 1];   // +1 pad: conflict-free scalar reads
    __shared__ float Ws[IN_C * HID];         // 8 KB
    int tid = threadIdx.x;
    for (int i = tid; i < IN_C * HID; i += 256) Ws[i] = W1[i];

    long long base = (long long)blockIdx.x * MMTILE;
    int rows = (int)((Nn - base) < MMTILE ? (Nn - base) : MMTILE);

    // coalesced float4 loads of the x tile
    const float4* xin = (const float4*)(x + base * IN_C);
    for (int i = tid; i < rows * (IN_C / 4); i += 256) {
        int r = i >> 5, k4 = i & 31;
        float4 v = xin[(long long)r * (IN_C / 4) + k4];
        xs[r][k4 * 4 + 0] = v.x; xs[r][k4 * 4 + 1] = v.y;
        xs[r][k4 * 4 + 2] = v.z; xs[r][k4 * 4 + 3] = v.w;
    }
    __syncthreads();

    int row = tid >> 2;          // 0..63
    int q   = tid & 3;           // output quad: j = q*4 .. q*4+3
    if (row >= rows) return;
    float4 acc = make_float4(0.f, 0.f, 0.f, 0.f);
#pragma unroll 8
    for (int k = 0; k < IN_C; k++) {
        float xv = xs[row][k];
        float4 w = *(const float4*)&Ws[k * HID + q * 4];
        acc.x += xv * w.x; acc.y += xv * w.y; acc.z += xv * w.z; acc.w += xv * w.w;
    }
    float d = g_dinv[base + row];
    acc.x *= d; acc.y *= d; acc.z *= d; acc.w *= d;
    *(float4*)&g_h1s[(base + row) * HID + q * 4] = acc;
}

// Generic 16-dim edge scatter: dst[c] += src[r]   (one thread per edge)
__global__ __launch_bounds__(256) void agg_kernel(const void* ei, long long E,
                                                  const float* __restrict__ src,
                                                  float* __restrict__ dst) {
    long long e = (long long)blockIdx.x * blockDim.x + threadIdx.x;
    if (e >= E) return;
    long long r, c;
    if (g_is32) {
        const int* p = (const int*)ei;
        r = p[e]; c = p[E + e];
    } else {
        const long long* p = (const long long*)ei;
        r = p[e]; c = p[E + e];
    }
    const float4* h = (const float4*)(src + r * HID);
    float* d = dst + c * HID;
    float4 v0 = h[0], v1 = h[1], v2 = h[2], v3 = h[3];
    red_add_f4(d + 0,  v0);
    red_add_f4(d + 4,  v1);
    red_add_f4(d + 8,  v2);
    red_add_f4(d + 12, v3);
}

// zs = relu(dinv*(a1 + h1s) + b1) * dinv      (per-thread float4)
__global__ void fin1_kernel(const float* __restrict__ b1, long long Nn) {
    long long t = (long long)blockIdx.x * blockDim.x + threadIdx.x;
    if (t >= Nn * (HID / 4)) return;
    long long row = t >> 2;
    int q = (int)(t & 3);
    float d = g_dinv[row];
    float4 a = *(const float4*)&g_a1 [row * HID + q * 4];
    float4 h = *(const float4*)&g_h1s[row * HID + q * 4];
    float4 b = *(const float4*)&b1[q * 4];
    float4 z;
    z.x = fmaxf(d * (a.x + h.x) + b.x, 0.f) * d;
    z.y = fmaxf(d * (a.y + h.y) + b.y, 0.f) * d;
    z.z = fmaxf(d * (a.z + h.z) + b.z, 0.f) * d;
    z.w = fmaxf(d * (a.w + h.w) + b.w, 0.f) * d;
    *(float4*)&g_zs[row * HID + q * 4] = z;
}

// out = (dinv*(a2 + zs)) @ W2 + b2      (fused GEMM + finalize, 4 threads/row)
__global__ __launch_bounds__(256) void mm2fin_kernel(const float* __restrict__ W2,
                                                     const float* __restrict__ b2,
                                                     float* __restrict__ out,
                                                     long long Nn) {
    __shared__ float Ws[HID * OUTC];   // 4 KB
    int tid = threadIdx.x;
    for (int i = tid; i < HID * OUTC; i += 256) Ws[i] = W2[i];
    __syncthreads();

    long long base = (long long)blockIdx.x * MMTILE;
    int row = tid >> 2;                // 0..63
    int q   = tid & 3;                 // outputs j = q*16 .. q*16+15
    long long r = base + row;
    if (r >= Nn) return;

    float d = g_dinv[r];
    float v[HID];
#pragma unroll
    for (int k4 = 0; k4 < HID / 4; k4++) {
        float4 a = *(const float4*)&g_a2[r * HID + k4 * 4];
        float4 z = *(const float4*)&g_zs[r * HID + k4 * 4];
        v[k4 * 4 + 0] = d * (a.x + z.x);
        v[k4 * 4 + 1] = d * (a.y + z.y);
        v[k4 * 4 + 2] = d * (a.z + z.z);
        v[k4 * 4 + 3] = d * (a.w + z.w);
    }
    float acc[16];
#pragma unroll
    for (int j = 0; j < 16; j++) acc[j] = 0.f;
#pragma unroll
    for (int k = 0; k < HID; k++) {
        float xv = v[k];
        const float* w = &Ws[k * OUTC + q * 16];
#pragma unroll
        for (int j = 0; j < 16; j++) acc[j] += xv * w[j];
    }
    float* o = out + r * OUTC + q * 16;
#pragma unroll
    for (int j4 = 0; j4 < 4; j4++) {
        float4 bb = *(const float4*)&b2[q * 16 + j4 * 4];
        float4 ov = make_float4(acc[j4*4+0] + bb.x, acc[j4*4+1] + bb.y,
                                acc[j4*4+2] + bb.z, acc[j4*4+3] + bb.w);
        *(float4*)&o[j4 * 4] = ov;
    }
}

// ---------------- launch ----------------------------------------------------
extern "C" void kernel_launch(void* const* d_in, const int* in_sizes, int n_in,
                              void* d_out, int out_size) {
    const float* x  = (const float*)d_in[0];
    const void*  ei = d_in[1];
    const float* W1 = (const float*)d_in[2];
    const float* b1 = (const float*)d_in[3];
    const float* W2 = (const float*)d_in[4];
    const float* b2 = (const float*)d_in[5];
    float* out = (float*)d_out;

    long long Nn = in_sizes[0] / IN_C;
    long long E  = (long long)in_sizes[1] / 2;

    float* p_dinv; cudaGetSymbolAddress((void**)&p_dinv, g_dinv);
    float* p_a1;   cudaGetSymbolAddress((void**)&p_a1,   g_a1);
    float* p_a2;   cudaGetSymbolAddress((void**)&p_a2,   g_a2);
    float* p_h1s;  cudaGetSymbolAddress((void**)&p_h1s,  g_h1s);

    cudaMemsetAsync(p_dinv, 0, Nn * sizeof(float));
    cudaMemsetAsync(p_a1,   0, Nn * HID * sizeof(float));
    cudaMemsetAsync(p_a2,   0, Nn * HID * sizeof(float));

    detect_kernel<<<1, 256>>>(ei, E, Nn);

    const int T = 256;
    unsigned gE = (unsigned)((E + T - 1) / T);
    unsigned gN = (unsigned)((Nn + T - 1) / T);
    unsigned gM = (unsigned)((Nn + MMTILE - 1) / MMTILE);

    deg_kernel  <<<gE, T>>>(ei, E);
    dinv_kernel <<<gN, T>>>(Nn);

    mm1_kernel  <<<gM, T>>>(x, W1, Nn);
    agg_kernel  <<<gE, T>>>(ei, E, p_h1s, p_a1);
    fin1_kernel <<<(unsigned)((Nn * (HID/4) + T - 1) / T), T>>>(b1, Nn);

    float* p_zs; cudaGetSymbolAddress((void**)&p_zs, g_zs);
    agg_kernel  <<<gE, T>>>(ei, E, p_zs, p_a2);
    mm2fin_kernel<<<gM, T>>>(W2, b2, out, Nn);
}

// round 4
// speedup vs baseline: 3.0769x; 1.4744x over previous
#include <cuda_runtime.h>
#include <cstdint>

// GCNEncoder: N=100000, E=3200000, 128 -> 16 -> 64
#define NMAX   100000
#define EMAX   3200000
#define IN_C   128
#define HID    16
#define OUTC   64
#define SCHUNK 1024   // scan chunk (256 threads * 4)

// ---------------- scratch (__device__ globals; no allocations allowed) ------
__device__ float g_dinv[NMAX];
__device__ int   g_cnt [NMAX];            // in-degree histogram
__device__ int   g_cur [NMAX];            // fill cursors
__device__ int   g_rowptr[NMAX + 1];      // CSR offsets (by destination)
__device__ int   g_bsum[256];             // scan block sums
__device__ int   g_boff[256];             // scanned block offsets
__device__ int   g_csrc[EMAX];            // CSR source indices
__device__ float g_h1s [NMAX * HID];      // (x @ W1) * dinv[row]
__device__ float g_zs  [NMAX * HID];      // relu(out1) * dinv[row]
__device__ int   g_is32;

// ---------------- kernels ----------------------------------------------------

__global__ void detect_kernel(const void* ei, long long words, long long n_nodes) {
    __shared__ int s;
    if (threadIdx.x == 0) s = 0;
    __syncthreads();
    long long cnt = words < 1024 ? words : 1024;
    const long long* p = (const long long*)ei;
    for (long long i = threadIdx.x; i < cnt; i += blockDim.x)
        if ((unsigned long long)p[i] >= (unsigned long long)n_nodes) s = 1;
    __syncthreads();
    if (threadIdx.x == 0) g_is32 = s;
}

// In-degree histogram over destinations (col).
__global__ void deg_kernel(const void* ei, long long E) {
    long long e = (long long)blockIdx.x * blockDim.x + threadIdx.x;
    if (e >= E) return;
    int c;
    if (g_is32) c = ((const int*)ei)[E + e];
    else        c = (int)((const long long*)ei)[E + e];
    atomicAdd(&g_cnt[c], 1);
}

__global__ void dinv_kernel(long long Nn) {
    long long i = (long long)blockIdx.x * blockDim.x + threadIdx.x;
    if (i >= Nn) return;
    g_dinv[i] = rsqrtf((float)g_cnt[i] + 1.0f);   // +1: self loop
}

// ---- 3-phase exclusive scan of g_cnt -> g_rowptr ----------------------------
__global__ __launch_bounds__(256) void scan1_kernel(int n) {
    __shared__ int wsum[8];
    __shared__ int woff[8];
    int t = threadIdx.x;
    int base = blockIdx.x * SCHUNK + t * 4;
    int v0 = base + 0 < n ? g_cnt[base + 0] : 0;
    int v1 = base + 1 < n ? g_cnt[base + 1] : 0;
    int v2 = base + 2 < n ? g_cnt[base + 2] : 0;
    int v3 = base + 3 < n ? g_cnt[base + 3] : 0;
    int tsum = v0 + v1 + v2 + v3;
    int lane = t & 31, w = t >> 5;
    int x = tsum;
#pragma unroll
    for (int off = 1; off < 32; off <<= 1) {
        int y = __shfl_up_sync(0xffffffff, x, off);
        if (lane >= off) x += y;
    }
    if (lane == 31) wsum[w] = x;
    __syncthreads();
    if (t == 0) {
        int acc = 0;
#pragma unroll
        for (int i = 0; i < 8; i++) { int tmp = wsum[i]; woff[i] = acc; acc += tmp; }
        g_bsum[blockIdx.x] = acc;
    }
    __syncthreads();
    int excl = woff[w] + (x - tsum);
    if (base + 0 < n) g_rowptr[base + 0] = excl;
    if (base + 1 < n) g_rowptr[base + 1] = excl + v0;
    if (base + 2 < n) g_rowptr[base + 2] = excl + v0 + v1;
    if (base + 3 < n) g_rowptr[base + 3] = excl + v0 + v1 + v2;
}

__global__ void scan2_kernel(int nb) {
    if (threadIdx.x == 0) {
        int acc = 0;
        for (int i = 0; i < nb; i++) { int tmp = g_bsum[i]; g_boff[i] = acc; acc += tmp; }
    }
}

__global__ void scan3_kernel(long long Nn, long long E) {
    long long i = (long long)blockIdx.x * blockDim.x + threadIdx.x;
    if (i < Nn) g_rowptr[i] += g_boff[i / SCHUNK];
    if (i == 0) g_rowptr[Nn] = (int)E;
}

// Fill CSR: for each edge, place src into its destination's segment.
__global__ void fill_kernel(const void* ei, long long E) {
    long long e = (long long)blockIdx.x * blockDim.x + threadIdx.x;
    if (e >= E) return;
    int r, c;
    if (g_is32) {
        const int* p = (const int*)ei;
        r = p[e]; c = p[E + e];
    } else {
        const long long* p = (const long long*)ei;
        r = (int)p[e]; c = (int)p[E + e];
    }
    int pos = g_rowptr[c] + atomicAdd(&g_cur[c], 1);
    g_csrc[pos] = r;
}

// h1s = (x @ W1) * dinv[row]   (round-1 style: per-thread row, W1 in smem)
__global__ __launch_bounds__(128) void mm1_kernel(const float* __restrict__ x,
                                                  const float* __restrict__ W1,
                                                  long long Nn) {
    __shared__ float Ws[IN_C * HID];
    for (int i = threadIdx.x; i < IN_C * HID; i += 128) Ws[i] = W1[i];
    __syncthreads();
    long long r = (long long)blockIdx.x * blockDim.x + threadIdx.x;
    if (r >= Nn) return;
    float acc[HID];
#pragma unroll
    for (int j = 0; j < HID; j++) acc[j] = 0.f;
    const float4* xr = (const float4*)(x + r * IN_C);
#pragma unroll 4
    for (int k = 0; k < IN_C / 4; k++) {
        float4 v = xr[k];
        const float* w = &Ws[(k * 4) * HID];
#pragma unroll
        for (int j = 0; j < HID; j++)
            acc[j] += v.x * w[j] + v.y * w[HID + j] + v.z * w[2 * HID + j] + v.w * w[3 * HID + j];
    }
    float d = g_dinv[r];
    float4* o = (float4*)&g_h1s[r * HID];
#pragma unroll
    for (int q = 0; q < HID / 4; q++)
        o[q] = make_float4(acc[4*q] * d, acc[4*q+1] * d, acc[4*q+2] * d, acc[4*q+3] * d);
}

// Layer-1 CSR gather + fused fin1.  4-lane team per destination node.
// zs[c] = relu(dinv[c]*(sum_src h1s[src] + h1s[c]) + b1) * dinv[c]
__global__ __launch_bounds__(256) void agg1_kernel(const float* __restrict__ b1,
                                                   long long Nn) {
    long long t = (long long)blockIdx.x * blockDim.x + threadIdx.x;
    long long c = t >> 2;
    int q = (int)(t & 3);
    if (c >= Nn) return;
    int e = g_rowptr[c], end = g_rowptr[c + 1];
    const float4* H = (const float4*)g_h1s;
    float4 acc = make_float4(0.f, 0.f, 0.f, 0.f);
    for (; e + 1 < end; e += 2) {
        int s0 = g_csrc[e], s1 = g_csrc[e + 1];
        float4 f0 = H[(long long)s0 * 4 + q];
        float4 f1 = H[(long long)s1 * 4 + q];
        acc.x += f0.x; acc.y += f0.y; acc.z += f0.z; acc.w += f0.w;
        acc.x += f1.x; acc.y += f1.y; acc.z += f1.z; acc.w += f1.w;
    }
    if (e < end) {
        int s0 = g_csrc[e];
        float4 f0 = H[(long long)s0 * 4 + q];
        acc.x += f0.x; acc.y += f0.y; acc.z += f0.z; acc.w += f0.w;
    }
    float d = g_dinv[c];
    float4 self = H[c * 4 + q];
    float4 b = ((const float4*)b1)[q];
    float4 z;
    z.x = fmaxf(d * (acc.x + self.x) + b.x, 0.f) * d;
    z.y = fmaxf(d * (acc.y + self.y) + b.y, 0.f) * d;
    z.z = fmaxf(d * (acc.z + self.z) + b.z, 0.f) * d;
    z.w = fmaxf(d * (acc.w + self.w) + b.w, 0.f) * d;
    ((float4*)g_zs)[c * 4 + q] = z;
}

// Layer-2 CSR gather + fused GEMM (W2) + bias.  4-lane team per node.
// out[c] = (dinv[c]*(sum_src zs[src] + zs[c])) @ W2 + b2
__global__ __launch_bounds__(256) void agg2mm_kernel(const float* __restrict__ W2,
                                                     const float* __restrict__ b2,
                                                     float* __restrict__ out,
                                                     long long Nn) {
    __shared__ float Ws[HID * OUTC];   // 4 KB
    for (int i = threadIdx.x; i < HID * OUTC; i += 256) Ws[i] = W2[i];
    __syncthreads();

    long long t = (long long)blockIdx.x * blockDim.x + threadIdx.x;
    long long team = t >> 2;
    int q = (int)(t & 3);
    bool valid = team < Nn;
    long long c = valid ? team : (Nn - 1);

    int e = g_rowptr[c], end = g_rowptr[c + 1];
    const float4* Z = (const float4*)g_zs;
    float4 acc = make_float4(0.f, 0.f, 0.f, 0.f);
    for (; e + 1 < end; e += 2) {
        int s0 = g_csrc[e], s1 = g_csrc[e + 1];
        float4 f0 = Z[(long long)s0 * 4 + q];
        float4 f1 = Z[(long long)s1 * 4 + q];
        acc.x += f0.x; acc.y += f0.y; acc.z += f0.z; acc.w += f0.w;
        acc.x += f1.x; acc.y += f1.y; acc.z += f1.z; acc.w += f1.w;
    }
    if (e < end) {
        int s0 = g_csrc[e];
        float4 f0 = Z[(long long)s0 * 4 + q];
        acc.x += f0.x; acc.y += f0.y; acc.z += f0.z; acc.w += f0.w;
    }
    float d = g_dinv[c];
    float4 self = Z[c * 4 + q];
    float vq[4];
    vq[0] = d * (acc.x + self.x);
    vq[1] = d * (acc.y + self.y);
    vq[2] = d * (acc.z + self.z);
    vq[3] = d * (acc.w + self.w);

    // gather full v[16] across the 4-lane team via shuffles
    int lane = threadIdx.x & 31;
    int tbase = lane & ~3;
    float vv[HID];
#pragma unroll
    for (int k = 0; k < HID; k++)
        vv[k] = __shfl_sync(0xffffffff, vq[k & 3], tbase + (k >> 2));

    // this lane computes output columns [q*16, q*16+16)
    float o[16];
#pragma unroll
    for (int j4 = 0; j4 < 4; j4++) {
        float4 bb = ((const float4*)b2)[q * 4 + j4];
        o[j4*4+0] = bb.x; o[j4*4+1] = bb.y; o[j4*4+2] = bb.z; o[j4*4+3] = bb.w;
    }
#pragma unroll
    for (int k = 0; k < HID; k++) {
        float xv = vv[k];
        const float* w = &Ws[k * OUTC + q * 16];
#pragma unroll
        for (int j = 0; j < 16; j++) o[j] += xv * w[j];
    }
    if (valid) {
        float4* op = (float4*)(out + c * OUTC + q * 16);
#pragma unroll
        for (int j4 = 0; j4 < 4; j4++)
            op[j4] = make_float4(o[j4*4+0], o[j4*4+1], o[j4*4+2], o[j4*4+3]);
    }
}

// ---------------- launch ----------------------------------------------------
extern "C" void kernel_launch(void* const* d_in, const int* in_sizes, int n_in,
                              void* d_out, int out_size) {
    const float* x  = (const float*)d_in[0];
    const void*  ei = d_in[1];
    const float* W1 = (const float*)d_in[2];
    const float* b1 = (const float*)d_in[3];
    const float* W2 = (const float*)d_in[4];
    const float* b2 = (const float*)d_in[5];
    float* out = (float*)d_out;

    long long Nn = in_sizes[0] / IN_C;
    long long E  = (long long)in_sizes[1] / 2;

    int* p_cnt; cudaGetSymbolAddress((void**)&p_cnt, g_cnt);
    int* p_cur; cudaGetSymbolAddress((void**)&p_cur, g_cur);

    cudaMemsetAsync(p_cnt, 0, Nn * sizeof(int));
    cudaMemsetAsync(p_cur, 0, Nn * sizeof(int));

    const int T = 256;
    unsigned gE = (unsigned)((E + T - 1) / T);
    unsigned gN = (unsigned)((Nn + T - 1) / T);
    unsigned gT = (unsigned)((4 * Nn + T - 1) / T);
    int nb = (int)((Nn + SCHUNK - 1) / SCHUNK);

    detect_kernel<<<1, 256>>>(ei, E, Nn);
    deg_kernel   <<<gE, T>>>(ei, E);
    dinv_kernel  <<<gN, T>>>(Nn);
    scan1_kernel <<<nb, 256>>>((int)Nn);
    scan2_kernel <<<1, 32>>>(nb);
    scan3_kernel <<<gN, T>>>(Nn, E);
    fill_kernel  <<<gE, T>>>(ei, E);

    mm1_kernel   <<<(unsigned)((Nn + 127) / 128), 128>>>(x, W1, Nn);
    agg1_kernel  <<<gT, T>>>(b1, Nn);
    agg2mm_kernel<<<gT, T>>>(W2, b2, out, Nn);
}